// round 1
// baseline (speedup 1.0000x reference)
#include <cuda_runtime.h>

// QuantumConv1d: x(32,80,3000) -> conv(K=3,pad=1) to 4 ch -> normalize ->
// 4-qubit Rot circuit + CNOT chain -> <Z_q> -> linear 4->512 -> out(32,512,3000)
//
// Inputs (metadata order): x, W_pre(4,240), b_pre(4), W_post(512,4), b_post(512), q_weights(4,3)
// Output: float32 (B, 512, 3000)

#define TILE_L   128
#define THREADS  256
#define C_IN     80
#define L_IN     3000
#define OUT_CH   512
#define KW       3

__global__ __launch_bounds__(THREADS)
void qconv_kernel(const float* __restrict__ x,
                  const float* __restrict__ W_pre,
                  const float* __restrict__ b_pre,
                  const float* __restrict__ W_post,
                  const float* __restrict__ b_post,
                  const float* __restrict__ qw,
                  float* __restrict__ out)
{
    __shared__ float  x_s[C_IN][TILE_L + 2];
    __shared__ float  w_s[C_IN * 12];      // rearranged [c][k][q]
    __shared__ float4 ez_s[TILE_L];
    __shared__ float  bpre_s[4];

    const int tid  = threadIdx.x;
    const int tile = blockIdx.x;
    const int b    = blockIdx.y;
    const int l0   = tile * TILE_L;

    // --- stage W_pre rearranged so each c gives 3 broadcast float4 loads ---
    for (int i = tid; i < C_IN * 12; i += THREADS) {
        int c = i / 12; int r = i - c * 12; int k = r >> 2; int q = r & 3;
        w_s[i] = W_pre[q * (C_IN * KW) + c * KW + k];
    }
    if (tid < 4) bpre_s[tid] = b_pre[tid];

    // --- stage x tile [c][l0-1 .. l0+TILE_L] with zero padding ---
    const float* xb = x + (size_t)b * C_IN * L_IN;
    for (int i = tid; i < C_IN * (TILE_L + 2); i += THREADS) {
        int c = i / (TILE_L + 2);
        int j = i - c * (TILE_L + 2);
        int l = l0 - 1 + j;
        x_s[c][j] = (l >= 0 && l < L_IN) ? xb[c * L_IN + l] : 0.0f;
    }
    __syncthreads();

    // ================= Phase 1: per-position expz =================
    if (tid < TILE_L) {
        float pre0 = bpre_s[0], pre1 = bpre_s[1], pre2 = bpre_s[2], pre3 = bpre_s[3];
        #pragma unroll 4
        for (int c = 0; c < C_IN; c++) {
            float xa = x_s[c][tid], xb1 = x_s[c][tid + 1], xc = x_s[c][tid + 2];
            const float4* wr = (const float4*)&w_s[c * 12];
            float4 w0 = wr[0], w1 = wr[1], w2 = wr[2];
            pre0 += w0.x * xa + w1.x * xb1 + w2.x * xc;
            pre1 += w0.y * xa + w1.y * xb1 + w2.y * xc;
            pre2 += w0.z * xa + w1.z * xb1 + w2.z * xc;
            pre3 += w0.w * xa + w1.w * xb1 + w2.w * xc;
        }

        // normalize (matches reference v/||v||)
        float p2  = pre0 * pre0 + pre1 * pre1 + pre2 * pre2 + pre3 * pre3;
        float inv = rsqrtf(p2);

        float sr[16], si[16];
        #pragma unroll
        for (int j = 0; j < 16; j++) { sr[j] = 0.0f; si[j] = 0.0f; }
        sr[0] = pre0 * inv; sr[1] = pre1 * inv; sr[2] = pre2 * inv; sr[3] = pre3 * inv;

        // Rot(phi,theta,omega) on each wire i (wire i = bit (3-i), stride 8>>i)
        #pragma unroll
        for (int i = 0; i < 4; i++) {
            float phi = qw[i * 3 + 0], th = qw[i * 3 + 1], om = qw[i * 3 + 2];
            float sh, ch; sincosf(0.5f * th, &sh, &ch);
            float a = 0.5f * (phi + om), d = 0.5f * (phi - om);
            float sa, ca, sd, cd;
            sincosf(a, &sa, &ca);
            sincosf(d, &sd, &cd);
            // U00 = e^{-ia} c ; U01 = -e^{+id} s ; U10 = e^{-id} s ; U11 = e^{+ia} c
            float u00r =  ch * ca, u00i = -ch * sa;
            float u01r = -sh * cd, u01i = -sh * sd;
            float u10r =  sh * cd, u10i = -sh * sd;
            float u11r =  ch * ca, u11i =  ch * sa;
            const int s = 8 >> i;
            #pragma unroll
            for (int j = 0; j < 16; j++) {
                if ((j & s) == 0) {
                    const int j1 = j | s;
                    float ar = sr[j],  ai = si[j];
                    float br = sr[j1], bi = si[j1];
                    sr[j]  = u00r * ar - u00i * ai + u01r * br - u01i * bi;
                    si[j]  = u00r * ai + u00i * ar + u01r * bi + u01i * br;
                    sr[j1] = u10r * ar - u10i * ai + u11r * br - u11i * bi;
                    si[j1] = u10r * ai + u10i * ar + u11r * bi + u11i * br;
                }
            }
        }

        // CNOT chain (pure index swaps; probs only, so swapping re/im suffices)
        #define SWP(A,B) { float t; t=sr[A]; sr[A]=sr[B]; sr[B]=t; t=si[A]; si[A]=si[B]; si[B]=t; }
        // cnot(0,1): ctrl bit3, tgt bit2
        SWP(8,12) SWP(9,13) SWP(10,14) SWP(11,15)
        // cnot(1,2): ctrl bit2, tgt bit1
        SWP(4,6)  SWP(5,7)  SWP(12,14) SWP(13,15)
        // cnot(2,3): ctrl bit1, tgt bit0
        SWP(2,3)  SWP(6,7)  SWP(10,11) SWP(14,15)
        #undef SWP

        float e0 = 0.f, e1 = 0.f, e2 = 0.f, e3 = 0.f;
        #pragma unroll
        for (int j = 0; j < 16; j++) {
            float p = sr[j] * sr[j] + si[j] * si[j];
            e0 += (j & 8) ? -p : p;
            e1 += (j & 4) ? -p : p;
            e2 += (j & 2) ? -p : p;
            e3 += (j & 1) ? -p : p;
        }
        ez_s[tid] = make_float4(e0, e1, e2, e3);
    }
    __syncthreads();

    // ================= Phase 2: 4->512 broadcast + coalesced stores =======
    const int lane  = tid & 31;
    const int wrp   = tid >> 5;                  // 8 warps
    const int lbase = l0 + lane * 4;             // 4 contiguous l per lane

    float4 ez0 = ez_s[lane * 4 + 0];
    float4 ez1 = ez_s[lane * 4 + 1];
    float4 ez2 = ez_s[lane * 4 + 2];
    float4 ez3 = ez_s[lane * 4 + 3];

    float* outb = out + (size_t)b * OUT_CH * L_IN;
    const bool full = (lbase + 3 < L_IN);

    for (int o = wrp; o < OUT_CH; o += 8) {
        float4 wp = __ldg((const float4*)(W_post + o * 4));   // warp-uniform broadcast
        float  bp = __ldg(b_post + o);
        float4 res;
        res.x = fmaf(wp.x, ez0.x, fmaf(wp.y, ez0.y, fmaf(wp.z, ez0.z, fmaf(wp.w, ez0.w, bp))));
        res.y = fmaf(wp.x, ez1.x, fmaf(wp.y, ez1.y, fmaf(wp.z, ez1.z, fmaf(wp.w, ez1.w, bp))));
        res.z = fmaf(wp.x, ez2.x, fmaf(wp.y, ez2.y, fmaf(wp.z, ez2.z, fmaf(wp.w, ez2.w, bp))));
        res.w = fmaf(wp.x, ez3.x, fmaf(wp.y, ez3.y, fmaf(wp.z, ez3.z, fmaf(wp.w, ez3.w, bp))));

        float* po = outb + (size_t)o * L_IN + lbase;
        if (full) {
            *(float4*)po = res;
        } else {
            if (lbase + 0 < L_IN) po[0] = res.x;
            if (lbase + 1 < L_IN) po[1] = res.y;
            if (lbase + 2 < L_IN) po[2] = res.z;
            if (lbase + 3 < L_IN) po[3] = res.w;
        }
    }
}

extern "C" void kernel_launch(void* const* d_in, const int* in_sizes, int n_in,
                              void* d_out, int out_size)
{
    const float* x      = (const float*)d_in[0];
    const float* W_pre  = (const float*)d_in[1];
    const float* b_pre  = (const float*)d_in[2];
    const float* W_post = (const float*)d_in[3];
    const float* b_post = (const float*)d_in[4];
    const float* qw     = (const float*)d_in[5];
    float* out = (float*)d_out;

    const int B = in_sizes[0] / (C_IN * L_IN);       // 32
    const int n_tiles = (L_IN + TILE_L - 1) / TILE_L; // 24

    dim3 grid(n_tiles, B);
    qconv_kernel<<<grid, THREADS>>>(x, W_pre, b_pre, W_post, b_post, qw, out);
}

// round 2
// speedup vs baseline: 1.0487x; 1.0487x over previous
#include <cuda_runtime.h>

// QuantumConv1d split into two kernels:
//  K1: conv(K=3) -> normalize -> 4-qubit circuit -> expz  -> g_ez (1.5MB, L2-resident)
//  K2: pure writer: out[b,o,l] = W_post[o,:] . ez[b,l,:] + b_post[o]  (196.6MB stores)

#define C_IN     80
#define L_IN     3000
#define OUT_CH   512
#define KW       3
#define TILE_L   128
#define B_MAX    32

__device__ float4 g_ez[B_MAX * L_IN];   // expz per (b,l), 1.5 MB scratch

// ===================== Kernel 1: expz compute =====================
__global__ __launch_bounds__(TILE_L)
void ez_kernel(const float* __restrict__ x,
               const float* __restrict__ W_pre,
               const float* __restrict__ b_pre,
               const float* __restrict__ qw)
{
    __shared__ float x_s[C_IN][TILE_L + 2];
    __shared__ float w_s[C_IN * 12];      // rearranged [c][k][q]
    __shared__ float bpre_s[4];

    const int tid = threadIdx.x;
    const int b   = blockIdx.y;
    const int l0  = blockIdx.x * TILE_L;

    for (int i = tid; i < C_IN * 12; i += TILE_L) {
        int c = i / 12; int r = i - c * 12; int k = r >> 2; int q = r & 3;
        w_s[i] = W_pre[q * (C_IN * KW) + c * KW + k];
    }
    if (tid < 4) bpre_s[tid] = b_pre[tid];

    const float* xb = x + (size_t)b * C_IN * L_IN;
    for (int i = tid; i < C_IN * (TILE_L + 2); i += TILE_L) {
        int c = i / (TILE_L + 2);
        int j = i - c * (TILE_L + 2);
        int l = l0 - 1 + j;
        x_s[c][j] = (l >= 0 && l < L_IN) ? xb[c * L_IN + l] : 0.0f;
    }
    __syncthreads();

    const int l = l0 + tid;
    if (l >= L_IN) return;

    float pre0 = bpre_s[0], pre1 = bpre_s[1], pre2 = bpre_s[2], pre3 = bpre_s[3];
    #pragma unroll 4
    for (int c = 0; c < C_IN; c++) {
        float xa = x_s[c][tid], xb1 = x_s[c][tid + 1], xc = x_s[c][tid + 2];
        const float4* wr = (const float4*)&w_s[c * 12];
        float4 w0 = wr[0], w1 = wr[1], w2 = wr[2];
        pre0 += w0.x * xa + w1.x * xb1 + w2.x * xc;
        pre1 += w0.y * xa + w1.y * xb1 + w2.y * xc;
        pre2 += w0.z * xa + w1.z * xb1 + w2.z * xc;
        pre3 += w0.w * xa + w1.w * xb1 + w2.w * xc;
    }

    float p2  = pre0 * pre0 + pre1 * pre1 + pre2 * pre2 + pre3 * pre3;
    float inv = rsqrtf(p2);

    float sr[16], si[16];
    #pragma unroll
    for (int j = 0; j < 16; j++) { sr[j] = 0.0f; si[j] = 0.0f; }
    sr[0] = pre0 * inv; sr[1] = pre1 * inv; sr[2] = pre2 * inv; sr[3] = pre3 * inv;

    // Rot(phi,theta,omega) on each wire i (wire i = bit (3-i), stride 8>>i)
    #pragma unroll
    for (int i = 0; i < 4; i++) {
        float phi = __ldg(qw + i * 3 + 0), th = __ldg(qw + i * 3 + 1), om = __ldg(qw + i * 3 + 2);
        float sh, ch; sincosf(0.5f * th, &sh, &ch);
        float a = 0.5f * (phi + om), d = 0.5f * (phi - om);
        float sa, ca, sd, cd;
        sincosf(a, &sa, &ca);
        sincosf(d, &sd, &cd);
        float u00r =  ch * ca, u00i = -ch * sa;
        float u01r = -sh * cd, u01i = -sh * sd;
        float u10r =  sh * cd, u10i = -sh * sd;
        float u11r =  ch * ca, u11i =  ch * sa;
        const int s = 8 >> i;
        #pragma unroll
        for (int j = 0; j < 16; j++) {
            if ((j & s) == 0) {
                const int j1 = j | s;
                float ar = sr[j],  ai = si[j];
                float br = sr[j1], bi = si[j1];
                sr[j]  = u00r * ar - u00i * ai + u01r * br - u01i * bi;
                si[j]  = u00r * ai + u00i * ar + u01r * bi + u01i * br;
                sr[j1] = u10r * ar - u10i * ai + u11r * br - u11i * bi;
                si[j1] = u10r * ai + u10i * ar + u11r * bi + u11i * br;
            }
        }
    }

    // CNOT chain: pure index swaps
    #define SWP(A,B) { float t; t=sr[A]; sr[A]=sr[B]; sr[B]=t; t=si[A]; si[A]=si[B]; si[B]=t; }
    SWP(8,12) SWP(9,13) SWP(10,14) SWP(11,15)   // cnot(0,1)
    SWP(4,6)  SWP(5,7)  SWP(12,14) SWP(13,15)   // cnot(1,2)
    SWP(2,3)  SWP(6,7)  SWP(10,11) SWP(14,15)   // cnot(2,3)
    #undef SWP

    float e0 = 0.f, e1 = 0.f, e2 = 0.f, e3 = 0.f;
    #pragma unroll
    for (int j = 0; j < 16; j++) {
        float p = sr[j] * sr[j] + si[j] * si[j];
        e0 += (j & 8) ? -p : p;
        e1 += (j & 4) ? -p : p;
        e2 += (j & 2) ? -p : p;
        e3 += (j & 1) ? -p : p;
    }
    g_ez[b * L_IN + l] = make_float4(e0, e1, e2, e3);
}

// ===================== Kernel 2: broadcast + store =====================
// grid: (24 l-tiles, 32 b, 8 o-groups of 64). block = 256.
// Each warp handles 8 o rows in its group; each lane owns 4 contiguous l.
#define OG 8
#define O_PER_GROUP (OUT_CH / OG)   // 64
#define O_PER_WARP  (O_PER_GROUP / 8) // 8

__global__ __launch_bounds__(256)
void write_kernel(const float* __restrict__ W_post,
                  const float* __restrict__ b_post,
                  float* __restrict__ out)
{
    __shared__ float4 ez_s[TILE_L];

    const int tid = threadIdx.x;
    const int b   = blockIdx.y;
    const int l0  = blockIdx.x * TILE_L;
    const int og  = blockIdx.z;

    if (tid < TILE_L) {
        int l = l0 + tid;
        ez_s[tid] = (l < L_IN) ? g_ez[b * L_IN + l] : make_float4(0.f, 0.f, 0.f, 0.f);
    }
    __syncthreads();

    const int lane = tid & 31;
    const int wrp  = tid >> 5;
    const int l4   = l0 + lane * 4;
    if (l4 >= L_IN) return;          // L_IN % 4 == 0: chunks never straddle

    const float4 e0 = ez_s[lane * 4 + 0];
    const float4 e1 = ez_s[lane * 4 + 1];
    const float4 e2 = ez_s[lane * 4 + 2];
    const float4 e3 = ez_s[lane * 4 + 3];

    float* outb = out + (size_t)b * OUT_CH * L_IN;

    #pragma unroll
    for (int i = 0; i < O_PER_WARP; i++) {
        const int o = og * O_PER_GROUP + i * 8 + wrp;
        const float4 wp = __ldg((const float4*)(W_post + o * 4));
        const float  bp = __ldg(b_post + o);
        float4 r;
        r.x = fmaf(wp.x, e0.x, fmaf(wp.y, e0.y, fmaf(wp.z, e0.z, fmaf(wp.w, e0.w, bp))));
        r.y = fmaf(wp.x, e1.x, fmaf(wp.y, e1.y, fmaf(wp.z, e1.z, fmaf(wp.w, e1.w, bp))));
        r.z = fmaf(wp.x, e2.x, fmaf(wp.y, e2.y, fmaf(wp.z, e2.z, fmaf(wp.w, e2.w, bp))));
        r.w = fmaf(wp.x, e3.x, fmaf(wp.y, e3.y, fmaf(wp.z, e3.z, fmaf(wp.w, e3.w, bp))));
        *(float4*)(outb + (size_t)o * L_IN + l4) = r;
    }
}

extern "C" void kernel_launch(void* const* d_in, const int* in_sizes, int n_in,
                              void* d_out, int out_size)
{
    const float* x      = (const float*)d_in[0];
    const float* W_pre  = (const float*)d_in[1];
    const float* b_pre  = (const float*)d_in[2];
    const float* W_post = (const float*)d_in[3];
    const float* b_post = (const float*)d_in[4];
    const float* qw     = (const float*)d_in[5];
    float* out = (float*)d_out;

    const int B = in_sizes[0] / (C_IN * L_IN);            // 32
    const int n_tiles = (L_IN + TILE_L - 1) / TILE_L;     // 24

    dim3 g1(n_tiles, B);
    ez_kernel<<<g1, TILE_L>>>(x, W_pre, b_pre, qw);

    dim3 g2(n_tiles, B, OG);
    write_kernel<<<g2, 256>>>(W_post, b_post, out);
}

// round 3
// speedup vs baseline: 1.0608x; 1.0116x over previous
#include <cuda_runtime.h>

// QuantumConv1d, 3-kernel pipeline:
//  K0 (1 thread): fold quantum circuit into 4 symmetric quadratic forms Q_q (4x4)
//  K1: conv(K=3) -> expz_q = (pre^T Q_q pre)/(pre^T pre) -> g_ez (1.5MB, L2-resident)
//  K2: writer: out[b,o,l] = W_post[o,:] . ez[b,l,:] + b_post[o]   (196.6MB streaming stores)

#define C_IN     80
#define L_IN     3000
#define OUT_CH   512
#define KW       3
#define TILE_L   128
#define B_MAX    32

__device__ float4 g_ez[B_MAX * L_IN];   // expz per (b,l)
__device__ float  g_Q[4][16];           // Q_q[k][m] row-major 4x4 per qubit q

// ===================== Kernel 0: build quadratic forms =====================
__global__ void setup_kernel(const float* __restrict__ qw)
{
    if (threadIdx.x != 0 || blockIdx.x != 0) return;

    // A[j][k]: final complex amplitude j given initial basis state k (k in 0..3)
    float Ar[16][4], Ai[16][4];

    for (int k = 0; k < 4; k++) {
        float sr[16], si[16];
        for (int j = 0; j < 16; j++) { sr[j] = 0.f; si[j] = 0.f; }
        sr[k] = 1.f;

        // Rot on each wire i (wire i = bit (3-i), stride 8>>i)
        for (int i = 0; i < 4; i++) {
            float phi = qw[i * 3 + 0], th = qw[i * 3 + 1], om = qw[i * 3 + 2];
            float sh, ch; sincosf(0.5f * th, &sh, &ch);
            float a = 0.5f * (phi + om), d = 0.5f * (phi - om);
            float sa, ca, sd, cd;
            sincosf(a, &sa, &ca);
            sincosf(d, &sd, &cd);
            float u00r =  ch * ca, u00i = -ch * sa;
            float u01r = -sh * cd, u01i = -sh * sd;
            float u10r =  sh * cd, u10i = -sh * sd;
            float u11r =  ch * ca, u11i =  ch * sa;
            const int s = 8 >> i;
            for (int j = 0; j < 16; j++) {
                if ((j & s) == 0) {
                    const int j1 = j | s;
                    float ar = sr[j],  ai = si[j];
                    float br = sr[j1], bi = si[j1];
                    sr[j]  = u00r * ar - u00i * ai + u01r * br - u01i * bi;
                    si[j]  = u00r * ai + u00i * ar + u01r * bi + u01i * br;
                    sr[j1] = u10r * ar - u10i * ai + u11r * br - u11i * bi;
                    si[j1] = u10r * ai + u10i * ar + u11r * bi + u11i * br;
                }
            }
        }
        // CNOT chain: index swaps
        const int perm_pairs[12][2] = {
            {8,12},{9,13},{10,14},{11,15},   // cnot(0,1)
            {4,6},{5,7},{12,14},{13,15},     // cnot(1,2)
            {2,3},{6,7},{10,11},{14,15}      // cnot(2,3)
        };
        for (int p = 0; p < 12; p++) {
            int a0 = perm_pairs[p][0], b0 = perm_pairs[p][1];
            float t;
            t = sr[a0]; sr[a0] = sr[b0]; sr[b0] = t;
            t = si[a0]; si[a0] = si[b0]; si[b0] = t;
        }
        for (int j = 0; j < 16; j++) { Ar[j][k] = sr[j]; Ai[j][k] = si[j]; }
    }

    // Q_q[k][m] = sum_j z_q[j] * (Ar[j][k]Ar[j][m] + Ai[j][k]Ai[j][m])
    for (int q = 0; q < 4; q++) {
        const int bit = 8 >> q;
        for (int k = 0; k < 4; k++)
            for (int m = 0; m < 4; m++) {
                float s = 0.f;
                for (int j = 0; j < 16; j++) {
                    float z = (j & bit) ? -1.f : 1.f;
                    s += z * (Ar[j][k] * Ar[j][m] + Ai[j][k] * Ai[j][m]);
                }
                g_Q[q][k * 4 + m] = s;
            }
    }
}

// ===================== Kernel 1: conv + quadratic forms =====================
__global__ __launch_bounds__(TILE_L)
void ez_kernel(const float* __restrict__ x,
               const float* __restrict__ W_pre,
               const float* __restrict__ b_pre)
{
    __shared__ float x_s[C_IN][TILE_L + 2];
    __shared__ float w_s[C_IN * 12];      // rearranged [c][k][q]
    __shared__ float bpre_s[4];
    __shared__ float Q_s[4][16];

    const int tid = threadIdx.x;
    const int b   = blockIdx.y;
    const int l0  = blockIdx.x * TILE_L;

    for (int i = tid; i < C_IN * 12; i += TILE_L) {
        int c = i / 12; int r = i - c * 12; int k = r >> 2; int q = r & 3;
        w_s[i] = W_pre[q * (C_IN * KW) + c * KW + k];
    }
    if (tid < 4)  bpre_s[tid] = b_pre[tid];
    if (tid < 64) ((float*)Q_s)[tid] = ((const float*)g_Q)[tid];

    const float* xb = x + (size_t)b * C_IN * L_IN;
    for (int i = tid; i < C_IN * (TILE_L + 2); i += TILE_L) {
        int c = i / (TILE_L + 2);
        int j = i - c * (TILE_L + 2);
        int l = l0 - 1 + j;
        x_s[c][j] = (l >= 0 && l < L_IN) ? xb[c * L_IN + l] : 0.0f;
    }
    __syncthreads();

    const int l = l0 + tid;
    if (l >= L_IN) return;

    float p0 = bpre_s[0], p1 = bpre_s[1], p2v = bpre_s[2], p3 = bpre_s[3];
    #pragma unroll 4
    for (int c = 0; c < C_IN; c++) {
        float xa = x_s[c][tid], xb1 = x_s[c][tid + 1], xc = x_s[c][tid + 2];
        const float4* wr = (const float4*)&w_s[c * 12];
        float4 w0 = wr[0], w1 = wr[1], w2 = wr[2];
        p0  += w0.x * xa + w1.x * xb1 + w2.x * xc;
        p1  += w0.y * xa + w1.y * xb1 + w2.y * xc;
        p2v += w0.z * xa + w1.z * xb1 + w2.z * xc;
        p3  += w0.w * xa + w1.w * xb1 + w2.w * xc;
    }

    const float n2  = p0 * p0 + p1 * p1 + p2v * p2v + p3 * p3;
    const float inv = __frcp_rn(n2);
    const float v[4] = { p0, p1, p2v, p3 };

    float e[4];
    #pragma unroll
    for (int q = 0; q < 4; q++) {
        float s = 0.f;
        #pragma unroll
        for (int k = 0; k < 4; k++) {
            float t = Q_s[q][k * 4 + 0] * v[0] + Q_s[q][k * 4 + 1] * v[1]
                    + Q_s[q][k * 4 + 2] * v[2] + Q_s[q][k * 4 + 3] * v[3];
            s += v[k] * t;
        }
        e[q] = s * inv;
    }
    g_ez[b * L_IN + l] = make_float4(e[0], e[1], e[2], e[3]);
}

// ===================== Kernel 2: broadcast + streaming stores =====================
// grid: (24 l-tiles, 32 b, 8 o-groups of 64). block = 256.
#define OG 8
#define O_PER_GROUP (OUT_CH / OG)     // 64
#define O_PER_WARP  (O_PER_GROUP / 8) // 8

__global__ __launch_bounds__(256)
void write_kernel(const float* __restrict__ W_post,
                  const float* __restrict__ b_post,
                  float* __restrict__ out)
{
    const int tid  = threadIdx.x;
    const int b    = blockIdx.y;
    const int l0   = blockIdx.x * TILE_L;
    const int og   = blockIdx.z;
    const int lane = tid & 31;
    const int wrp  = tid >> 5;
    const int l4   = l0 + lane * 4;
    if (l4 >= L_IN) return;           // L_IN % 4 == 0: no straddle

    const float4* ezp = (const float4*)&g_ez[b * L_IN + l4];
    const float4 e0 = __ldg(ezp + 0);
    const float4 e1 = __ldg(ezp + 1);
    const float4 e2 = __ldg(ezp + 2);
    const float4 e3 = __ldg(ezp + 3);

    float* outb = out + (size_t)b * OUT_CH * L_IN;

    #pragma unroll
    for (int i = 0; i < O_PER_WARP; i++) {
        const int o = og * O_PER_GROUP + i * 8 + wrp;
        const float4 wp = __ldg((const float4*)(W_post + o * 4));
        const float  bp = __ldg(b_post + o);
        float4 r;
        r.x = fmaf(wp.x, e0.x, fmaf(wp.y, e0.y, fmaf(wp.z, e0.z, fmaf(wp.w, e0.w, bp))));
        r.y = fmaf(wp.x, e1.x, fmaf(wp.y, e1.y, fmaf(wp.z, e1.z, fmaf(wp.w, e1.w, bp))));
        r.z = fmaf(wp.x, e2.x, fmaf(wp.y, e2.y, fmaf(wp.z, e2.z, fmaf(wp.w, e2.w, bp))));
        r.w = fmaf(wp.x, e3.x, fmaf(wp.y, e3.y, fmaf(wp.z, e3.z, fmaf(wp.w, e3.w, bp))));
        __stcs((float4*)(outb + (size_t)o * L_IN + l4), r);
    }
}

extern "C" void kernel_launch(void* const* d_in, const int* in_sizes, int n_in,
                              void* d_out, int out_size)
{
    const float* x      = (const float*)d_in[0];
    const float* W_pre  = (const float*)d_in[1];
    const float* b_pre  = (const float*)d_in[2];
    const float* W_post = (const float*)d_in[3];
    const float* b_post = (const float*)d_in[4];
    const float* qw     = (const float*)d_in[5];
    float* out = (float*)d_out;

    const int B = in_sizes[0] / (C_IN * L_IN);            // 32
    const int n_tiles = (L_IN + TILE_L - 1) / TILE_L;     // 24

    setup_kernel<<<1, 32>>>(qw);

    dim3 g1(n_tiles, B);
    ez_kernel<<<g1, TILE_L>>>(x, W_pre, b_pre);

    dim3 g2(n_tiles, B, OG);
    write_kernel<<<g2, 256>>>(W_post, b_post, out);
}

// round 4
// speedup vs baseline: 1.1778x; 1.1103x over previous
#include <cuda_runtime.h>

// QuantumConv1d, 2-kernel pipeline:
//  K1: warp0 folds circuit -> Q forms (inline, __sincosf + shuffles);
//      conv(K=3) -> expz_q = (pre^T Q_q pre)/(pre^T pre) -> g_ez (1.5MB, L2-resident)
//  K2: writer: out[b,o,l] = W_post[o,:] . ez[b,l,:] + b_post[o]  (196.6MB streaming stores)

#define C_IN     80
#define L_IN     3000
#define OUT_CH   512
#define KW       3
#define TILE_L   128
#define B_MAX    32

__device__ float4 g_ez[B_MAX * L_IN];   // expz per (b,l)

// ===================== Kernel 1: conv + inline Q + quadratic forms =====================
__global__ __launch_bounds__(TILE_L)
void ez_kernel(const float* __restrict__ x,
               const float* __restrict__ W_pre,
               const float* __restrict__ b_pre,
               const float* __restrict__ qw)
{
    __shared__ float x_s[C_IN][TILE_L + 2];
    __shared__ float w_s[C_IN * 12];      // rearranged [c][k][q]
    __shared__ float bpre_s[4];
    __shared__ float Q_s[4][16];          // Q_q 4x4 row-major per qubit

    const int tid = threadIdx.x;
    const int b   = blockIdx.y;
    const int l0  = blockIdx.x * TILE_L;

    // ---- stage small weights (all threads, cheap) ----
    for (int i = tid; i < C_IN * 12; i += TILE_L) {
        int c = i / 12; int r = i - c * 12; int k = r >> 2; int q = r & 3;
        w_s[i] = W_pre[q * (C_IN * KW) + c * KW + k];
    }
    if (tid < 4) bpre_s[tid] = b_pre[tid];

    if (tid < 32) {
        // ======== warp 0: circuit on basis column k = lane&3, fully unrolled ========
        const int k = tid & 3;
        float sr[16], si[16];
        #pragma unroll
        for (int j = 0; j < 16; j++) { sr[j] = 0.f; si[j] = 0.f; }
        #pragma unroll
        for (int j = 0; j < 4; j++) if (j == k) sr[j] = 1.f;

        #pragma unroll
        for (int i = 0; i < 4; i++) {
            float phi = __ldg(qw + i * 3 + 0), th = __ldg(qw + i * 3 + 1), om = __ldg(qw + i * 3 + 2);
            float sh, ch; __sincosf(0.5f * th, &sh, &ch);
            float a = 0.5f * (phi + om), d = 0.5f * (phi - om);
            float sa, ca, sd, cd;
            __sincosf(a, &sa, &ca);
            __sincosf(d, &sd, &cd);
            float u00r =  ch * ca, u00i = -ch * sa;
            float u01r = -sh * cd, u01i = -sh * sd;
            float u10r =  sh * cd, u10i = -sh * sd;
            float u11r =  ch * ca, u11i =  ch * sa;
            const int s = 8 >> i;
            #pragma unroll
            for (int j = 0; j < 16; j++) {
                if ((j & s) == 0) {
                    const int j1 = j | s;
                    float ar = sr[j],  ai = si[j];
                    float br = sr[j1], bi = si[j1];
                    sr[j]  = u00r * ar - u00i * ai + u01r * br - u01i * bi;
                    si[j]  = u00r * ai + u00i * ar + u01r * bi + u01i * br;
                    sr[j1] = u10r * ar - u10i * ai + u11r * br - u11i * bi;
                    si[j1] = u10r * ai + u10i * ar + u11r * bi + u11i * br;
                }
            }
        }
        // CNOT chain: static register swaps
        #define SWP(A,B) { float t; t=sr[A]; sr[A]=sr[B]; sr[B]=t; t=si[A]; si[A]=si[B]; si[B]=t; }
        SWP(8,12) SWP(9,13) SWP(10,14) SWP(11,15)   // cnot(0,1)
        SWP(4,6)  SWP(5,7)  SWP(12,14) SWP(13,15)   // cnot(1,2)
        SWP(2,3)  SWP(6,7)  SWP(10,11) SWP(14,15)   // cnot(2,3)
        #undef SWP

        // Q[q][k][m] via cross-column shuffles; lane holds column k.
        float Qv[4][4];
        #pragma unroll
        for (int q = 0; q < 4; q++)
            #pragma unroll
            for (int m = 0; m < 4; m++) Qv[q][m] = 0.f;

        #pragma unroll
        for (int j = 0; j < 16; j++) {
            #pragma unroll
            for (int m = 0; m < 4; m++) {
                float arm = __shfl_sync(0xffffffffu, sr[j], m);
                float aim = __shfl_sync(0xffffffffu, si[j], m);
                float p = sr[j] * arm + si[j] * aim;
                Qv[0][m] += (j & 8) ? -p : p;
                Qv[1][m] += (j & 4) ? -p : p;
                Qv[2][m] += (j & 2) ? -p : p;
                Qv[3][m] += (j & 1) ? -p : p;
            }
        }
        if (tid < 4) {
            #pragma unroll
            for (int q = 0; q < 4; q++)
                #pragma unroll
                for (int m = 0; m < 4; m++)
                    Q_s[q][tid * 4 + m] = Qv[q][m];
        }
    } else {
        // ======== warps 1-3: stage x tile ========
        const float* xb = x + (size_t)b * C_IN * L_IN;
        for (int i = tid - 32; i < C_IN * (TILE_L + 2); i += TILE_L - 32) {
            int c = i / (TILE_L + 2);
            int j = i - c * (TILE_L + 2);
            int l = l0 - 1 + j;
            x_s[c][j] = (l >= 0 && l < L_IN) ? xb[c * L_IN + l] : 0.0f;
        }
    }
    __syncthreads();

    const int l = l0 + tid;
    if (l >= L_IN) return;

    float p0 = bpre_s[0], p1 = bpre_s[1], p2v = bpre_s[2], p3 = bpre_s[3];
    #pragma unroll 4
    for (int c = 0; c < C_IN; c++) {
        float xa = x_s[c][tid], xb1 = x_s[c][tid + 1], xc = x_s[c][tid + 2];
        const float4* wr = (const float4*)&w_s[c * 12];
        float4 w0 = wr[0], w1 = wr[1], w2 = wr[2];
        p0  += w0.x * xa + w1.x * xb1 + w2.x * xc;
        p1  += w0.y * xa + w1.y * xb1 + w2.y * xc;
        p2v += w0.z * xa + w1.z * xb1 + w2.z * xc;
        p3  += w0.w * xa + w1.w * xb1 + w2.w * xc;
    }

    const float n2  = p0 * p0 + p1 * p1 + p2v * p2v + p3 * p3;
    const float inv = __frcp_rn(n2);
    const float v[4] = { p0, p1, p2v, p3 };

    float e[4];
    #pragma unroll
    for (int q = 0; q < 4; q++) {
        float s = 0.f;
        #pragma unroll
        for (int k = 0; k < 4; k++) {
            float t = Q_s[q][k * 4 + 0] * v[0] + Q_s[q][k * 4 + 1] * v[1]
                    + Q_s[q][k * 4 + 2] * v[2] + Q_s[q][k * 4 + 3] * v[3];
            s += v[k] * t;
        }
        e[q] = s * inv;
    }
    g_ez[b * L_IN + l] = make_float4(e[0], e[1], e[2], e[3]);
}

// ===================== Kernel 2: broadcast + streaming stores =====================
// grid: (24 l-tiles, 32 b). block = 512 (16 warps). Each warp sweeps o = wrp..511 step 16.
__global__ __launch_bounds__(512)
void write_kernel(const float* __restrict__ W_post,
                  const float* __restrict__ b_post,
                  float* __restrict__ out)
{
    const int tid  = threadIdx.x;
    const int b    = blockIdx.y;
    const int l0   = blockIdx.x * TILE_L;
    const int lane = tid & 31;
    const int wrp  = tid >> 5;                  // 0..15
    const int l4   = l0 + lane * 4;
    if (l4 >= L_IN) return;                     // L_IN % 4 == 0: no straddle

    const float4* ezp = (const float4*)&g_ez[b * L_IN + l4];
    const float4 e0 = __ldg(ezp + 0);
    const float4 e1 = __ldg(ezp + 1);
    const float4 e2 = __ldg(ezp + 2);
    const float4 e3 = __ldg(ezp + 3);

    float* outb = out + (size_t)b * OUT_CH * L_IN;

    #pragma unroll 8
    for (int o = wrp; o < OUT_CH; o += 16) {
        const float4 wp = __ldg((const float4*)(W_post + o * 4));
        const float  bp = __ldg(b_post + o);
        float4 r;
        r.x = fmaf(wp.x, e0.x, fmaf(wp.y, e0.y, fmaf(wp.z, e0.z, fmaf(wp.w, e0.w, bp))));
        r.y = fmaf(wp.x, e1.x, fmaf(wp.y, e1.y, fmaf(wp.z, e1.z, fmaf(wp.w, e1.w, bp))));
        r.z = fmaf(wp.x, e2.x, fmaf(wp.y, e2.y, fmaf(wp.z, e2.z, fmaf(wp.w, e2.w, bp))));
        r.w = fmaf(wp.x, e3.x, fmaf(wp.y, e3.y, fmaf(wp.z, e3.z, fmaf(wp.w, e3.w, bp))));
        __stcs((float4*)(outb + (size_t)o * L_IN + l4), r);
    }
}

extern "C" void kernel_launch(void* const* d_in, const int* in_sizes, int n_in,
                              void* d_out, int out_size)
{
    const float* x      = (const float*)d_in[0];
    const float* W_pre  = (const float*)d_in[1];
    const float* b_pre  = (const float*)d_in[2];
    const float* W_post = (const float*)d_in[3];
    const float* b_post = (const float*)d_in[4];
    const float* qw     = (const float*)d_in[5];
    float* out = (float*)d_out;

    const int B = in_sizes[0] / (C_IN * L_IN);            // 32
    const int n_tiles = (L_IN + TILE_L - 1) / TILE_L;     // 24

    dim3 g1(n_tiles, B);
    ez_kernel<<<g1, TILE_L>>>(x, W_pre, b_pre, qw);

    dim3 g2(n_tiles, B);
    write_kernel<<<g2, 512>>>(W_post, b_post, out);
}